// round 6
// baseline (speedup 1.0000x reference)
#include <cuda_runtime.h>
#include <math.h>

#define Bn 8
#define Cn 64
#define On 64
#define Hn 128
#define Wn 128
#define HWn 16384
#define KKn 9

// scratch for sigmoid(mask conv): 8*9*128*128 floats = 4.7MB
__device__ float g_mask[Bn * KKn * HWn];

// ---------------------------------------------------------------------------
// Kernel A: fused 3x3 conv -> 18 offset channels + 9 mask channels (sigmoid).
// Block = one row (128px) of one batch, 256 threads, tile 4px x 4oc.
// Balanced lane map: warp = 8 px-groups x 4 oc-groups (32px x 16oc).
// Double-buffered staging: load chunk n+1 while computing chunk n.
// ---------------------------------------------------------------------------
__global__ __launch_bounds__(256) void conv_offmask_kernel(
    const float* __restrict__ x,
    const float* __restrict__ p_w, const float* __restrict__ p_b,
    const float* __restrict__ m_w, const float* __restrict__ m_b,
    float* __restrict__ offs_out)
{
    __shared__ float sX[2][8 * 3 * 132];   // 2 x 12672 B
    __shared__ float sW[2][72 * 36];       // 2 x 10368 B

    const int h = blockIdx.x, b = blockIdx.y;
    const int tid = threadIdx.x;
    const int warp = tid >> 5, lane = tid & 31;
    const int px4 = ((warp & 3) * 8 + (lane & 7)) * 4;   // 4 pixels
    const int oc  = ((warp >> 2) * 4 + (lane >> 3)) * 4; // 4 out channels
    const int row = h * Wn;

    auto stage = [&](int c0, int buf) {
        for (int e = tid; e < 3168; e += 256) {
            int c = e / 396;
            int rem = e - c * 396;
            int r = rem / 132;
            int i = rem - r * 132;
            int y = h - 1 + r, xc = i - 1;
            float v = 0.f;
            if ((unsigned)y < Hn && (unsigned)xc < Wn)
                v = x[(((size_t)(b * Cn + c0 + c)) << 14) + y * Wn + xc];
            sX[buf][e] = v;
        }
        #pragma unroll 2
        for (int e = tid; e < 72 * 36; e += 256) {
            int o = e / 72, kk = e - o * 72;
            float v = 0.f;
            if (o < 18)      v = p_w[o * 576 + c0 * 9 + kk];
            else if (o < 27) v = m_w[(o - 18) * 576 + c0 * 9 + kk];
            sW[buf][kk * 36 + o] = v;
        }
    };

    float acc[4][4] = {};

    stage(0, 0);
    __syncthreads();

    for (int n = 0; n < 8; ++n) {
        int cur = n & 1;
        if (n < 7) stage((n + 1) * 8, cur ^ 1);

        #pragma unroll
        for (int c = 0; c < 8; ++c) {
            #pragma unroll
            for (int ki = 0; ki < 3; ++ki) {
                const float* rowp = sX[cur] + c * 396 + ki * 132;
                float4 X0 = *(const float4*)&rowp[px4];
                float2 X1 = *(const float2*)&rowp[px4 + 4];
                float xs[6] = {X0.x, X0.y, X0.z, X0.w, X1.x, X1.y};
                int kkb = c * 9 + ki * 3;
                #pragma unroll
                for (int kj = 0; kj < 3; ++kj) {
                    float4 wv = *(const float4*)&sW[cur][(kkb + kj) * 36 + oc];
                    #pragma unroll
                    for (int r = 0; r < 4; ++r) {
                        float a = xs[r + kj];
                        acc[r][0] = fmaf(a, wv.x, acc[r][0]);
                        acc[r][1] = fmaf(a, wv.y, acc[r][1]);
                        acc[r][2] = fmaf(a, wv.z, acc[r][2]);
                        acc[r][3] = fmaf(a, wv.w, acc[r][3]);
                    }
                }
            }
        }
        __syncthreads();
    }

    #pragma unroll
    for (int q = 0; q < 4; ++q) {
        int o = oc + q;
        if (o < 18) {
            float bias = p_b[o];
            float* dst = offs_out + (((size_t)(b * 18 + o)) << 14) + row;
            float4 v = make_float4(acc[0][q] + bias, acc[1][q] + bias,
                                   acc[2][q] + bias, acc[3][q] + bias);
            *(float4*)&dst[px4] = v;
        } else if (o < 27) {
            float bias = m_b[o - 18];
            float* dst = g_mask + (((size_t)(b * 9 + (o - 18))) << 14) + row;
            float4 v;
            v.x = 1.f / (1.f + expf(-(acc[0][q] + bias)));
            v.y = 1.f / (1.f + expf(-(acc[1][q] + bias)));
            v.z = 1.f / (1.f + expf(-(acc[2][q] + bias)));
            v.w = 1.f / (1.f + expf(-(acc[3][q] + bias)));
            *(float4*)&dst[px4] = v;
        }
    }
}

// ---------------------------------------------------------------------------
// Kernel B: modulated deformable conv as tiled SGEMM, software-pipelined.
// Block = one output row (128 px) x 64 oc, 256 threads, K-chunk = 4 input
// channels (36 kk), double-buffered sA/sW: gather chunk n+1 overlaps GEMM on
// chunk n; one barrier per chunk. Thread tile 4px x 8oc; balanced lane map.
// Bilinear corners precomputed as short4 + folded weights.
// ---------------------------------------------------------------------------
__global__ __launch_bounds__(256, 2) void deform_kernel(
    const float* __restrict__ x,
    const float* __restrict__ offs,
    const float* __restrict__ d_w, const float* __restrict__ d_b,
    float* __restrict__ out)
{
    extern __shared__ float smem[];
    float* sA0 = smem;                          // 36*128 = 18432 B
    float* sA1 = sA0 + 36 * 128;                // 18432 B
    float* sW0 = sA1 + 36 * 128;                // 36*68 = 9792 B
    float* sW1 = sW0 + 36 * 68;                 // 9792 B
    short4* spos = (short4*)(sW1 + 36 * 68);    // 9*128*8  = 9216 B
    float4* swt  = (float4*)(spos + KKn * Wn);  // 9*128*16 = 18432 B

    const int h = blockIdx.x, b = blockIdx.y;
    const int tid = threadIdx.x;
    const int warp = tid >> 5, lane = tid & 31;
    const int px4 = ((warp & 3) * 8 + (lane & 7)) * 4;   // 4 pixels
    const int oc8 = ((warp >> 2) * 4 + (lane >> 3)) * 8; // 8 out channels
    const int row = h * Wn;

    // precompute bilinear corner indices + (mask*validity)-folded weights
    for (int e = tid; e < KKn * Wn; e += 256) {
        int i = e & 127, k = e >> 7;
        float dy = offs[(((size_t)(b * 18 + 2 * k)) << 14) + row + i];
        float dx = offs[(((size_t)(b * 18 + 2 * k + 1)) << 14) + row + i];
        float m  = g_mask[(((size_t)(b * 9 + k)) << 14) + row + i];
        int ki = k / 3, kj = k - ki * 3;
        float py = (float)(h - 1 + ki) + dy;
        float px = (float)(i - 1 + kj) + dx;
        float y0f = floorf(py), x0f = floorf(px);
        float fy = py - y0f, fx = px - x0f;
        int y0 = (int)y0f, x0 = (int)x0f;
        int y1 = y0 + 1, x1 = x0 + 1;
        float vy0 = ((unsigned)y0 < Hn) ? 1.f : 0.f;
        float vy1 = ((unsigned)y1 < Hn) ? 1.f : 0.f;
        float vx0 = ((unsigned)x0 < Wn) ? 1.f : 0.f;
        float vx1 = ((unsigned)x1 < Wn) ? 1.f : 0.f;
        float gy = 1.f - fy, gx = 1.f - fx;
        float4 wq;
        wq.x = gy * gx * m * vy0 * vx0;
        wq.y = gy * fx * m * vy0 * vx1;
        wq.z = fy * gx * m * vy1 * vx0;
        wq.w = fy * fx * m * vy1 * vx1;
        int cy0 = min(max(y0, 0), Hn - 1) * Wn;
        int cy1 = min(max(y1, 0), Hn - 1) * Wn;
        int cx0 = min(max(x0, 0), Wn - 1);
        int cx1 = min(max(x1, 0), Wn - 1);
        short4 sp;
        sp.x = (short)(cy0 + cx0);
        sp.y = (short)(cy0 + cx1);
        sp.z = (short)(cy1 + cx0);
        sp.w = (short)(cy1 + cx1);
        spos[e] = sp;
        swt[e]  = wq;
    }

    const int px_g = tid & 127;         // gather: this thread's pixel
    const int half = tid >> 7;          // gather: channel half (0/1 -> 2 ch)

    auto stage = [&](int c0, float* sA, float* sW) {
        // weight stage first: independent LDGs in flight (36 kk x 64 oc)
        #pragma unroll
        for (int j = 0; j < 9; ++j) {
            int e = tid + j * 256;
            int o = e / 36, kk = e - o * 36;
            sW[kk * 68 + o] = d_w[o * 576 + c0 * 9 + kk];
        }
        const float* pl = x + (((size_t)(b * Cn + c0 + half * 2)) << 14);
        #pragma unroll 3
        for (int t = 0; t < KKn; ++t) {
            short4 sp = spos[t * 128 + px_g];
            float4 w4 = swt[t * 128 + px_g];
            int p0 = sp.x, p1 = sp.y, p2 = sp.z, p3 = sp.w;
            const float* p = pl;
            #pragma unroll
            for (int c = 0; c < 2; ++c) {
                float v = w4.x * __ldg(p + p0)
                        + w4.y * __ldg(p + p1)
                        + w4.z * __ldg(p + p2)
                        + w4.w * __ldg(p + p3);
                sA[((half * 2 + c) * 9 + t) * 128 + px_g] = v;
                p += HWn;
            }
        }
    };

    float acc[4][8] = {};

    __syncthreads();            // spos/swt ready
    stage(0, sA0, sW0);
    __syncthreads();

    for (int n = 0; n < 16; ++n) {
        float* curA = (n & 1) ? sA1 : sA0;
        float* curW = (n & 1) ? sW1 : sW0;
        if (n < 15) {
            float* nxtA = (n & 1) ? sA0 : sA1;
            float* nxtW = (n & 1) ? sW0 : sW1;
            stage((n + 1) * 4, nxtA, nxtW);
        }

        #pragma unroll 4
        for (int kk = 0; kk < 36; ++kk) {
            float4 av = *(const float4*)&curA[kk * 128 + px4];
            float4 w0 = *(const float4*)&curW[kk * 68 + oc8];
            float4 w1 = *(const float4*)&curW[kk * 68 + oc8 + 4];
            float wv[8] = {w0.x, w0.y, w0.z, w0.w, w1.x, w1.y, w1.z, w1.w};
            float ar[4] = {av.x, av.y, av.z, av.w};
            #pragma unroll
            for (int r = 0; r < 4; ++r)
                #pragma unroll
                for (int q = 0; q < 8; ++q)
                    acc[r][q] = fmaf(ar[r], wv[q], acc[r][q]);
        }
        __syncthreads();
    }

    #pragma unroll
    for (int q = 0; q < 8; ++q) {
        int o = oc8 + q;
        float bias = __ldg(d_b + o);
        float* dst = out + (((size_t)(b * On + o)) << 14) + row;
        float4 v = make_float4(acc[0][q] + bias, acc[1][q] + bias,
                               acc[2][q] + bias, acc[3][q] + bias);
        *(float4*)&dst[px4] = v;
    }
}

// ---------------------------------------------------------------------------

extern "C" void kernel_launch(void* const* d_in, const int* in_sizes, int n_in,
                              void* d_out, int out_size) {
    const float* x    = (const float*)d_in[0];
    const float* p_w  = (const float*)d_in[1];
    const float* p_b  = (const float*)d_in[2];
    const float* m_w  = (const float*)d_in[3];
    const float* m_b  = (const float*)d_in[4];
    const float* d_wp = (const float*)d_in[5];
    const float* d_bp = (const float*)d_in[6];

    float* out = (float*)d_out;                         // [8,64,128,128]
    float* offs_out = out + (size_t)Bn * On * HWn;      // [8,18,128,128]

    const int smemB = (2 * 36 * 128 + 2 * 36 * 68) * 4
                    + KKn * Wn * (8 + 16);              // 84096
    cudaFuncSetAttribute(deform_kernel,
                         cudaFuncAttributeMaxDynamicSharedMemorySize, smemB);

    dim3 grid(Hn, Bn);
    conv_offmask_kernel<<<grid, 256>>>(x, p_w, p_b, m_w, m_b, offs_out);
    deform_kernel<<<grid, 256, smemB>>>(x, offs_out, d_wp, d_bp, out);
}

// round 7
// speedup vs baseline: 1.0839x; 1.0839x over previous
#include <cuda_runtime.h>
#include <math.h>

#define Bn 8
#define Cn 64
#define On 64
#define Hn 128
#define Wn 128
#define HWn 16384
#define KKn 9

// scratch for sigmoid(mask conv): 8*9*128*128 floats = 4.7MB
__device__ float g_mask[Bn * KKn * HWn];

// ---------------------------------------------------------------------------
// Kernel A: fused 3x3 conv -> 18 offset channels + 9 mask channels (sigmoid).
// Block = one row (128px) of one batch, 256 threads, tile 4px x 4oc.
// Balanced lane map: warp = 8 px-groups x 4 oc-groups (32px x 16oc).
// ---------------------------------------------------------------------------
__global__ __launch_bounds__(256) void conv_offmask_kernel(
    const float* __restrict__ x,
    const float* __restrict__ p_w, const float* __restrict__ p_b,
    const float* __restrict__ m_w, const float* __restrict__ m_b,
    float* __restrict__ offs_out)
{
    __shared__ float sX[8 * 3 * 132];   // 12672 B
    __shared__ float sW[72 * 36];       // 10368 B

    const int h = blockIdx.x, b = blockIdx.y;
    const int tid = threadIdx.x;
    const int warp = tid >> 5, lane = tid & 31;
    const int px4 = ((warp & 3) * 8 + (lane & 7)) * 4;   // 4 pixels
    const int oc  = ((warp >> 2) * 4 + (lane >> 3)) * 4; // 4 out channels
    const int row = h * Wn;

    float acc[4][4] = {};

    for (int c0 = 0; c0 < Cn; c0 += 8) {
        __syncthreads();
        // stage 3 raw rows x 8 channels, width 132 (zero-pad halo)
        for (int e = tid; e < 3168; e += 256) {
            int c = e / 396;
            int rem = e - c * 396;
            int r = rem / 132;
            int i = rem - r * 132;
            int y = h - 1 + r, xc = i - 1;
            float v = 0.f;
            if ((unsigned)y < Hn && (unsigned)xc < Wn)
                v = x[(((size_t)(b * Cn + c0 + c)) << 14) + y * Wn + xc];
            sX[e] = v;
        }
        // stage weights for this chunk: sW[kk_local][o], o padded to 36
        #pragma unroll 2
        for (int e = tid; e < 72 * 36; e += 256) {
            int o = e / 72, kk = e - o * 72;
            float v = 0.f;
            if (o < 18)      v = p_w[o * 576 + c0 * 9 + kk];
            else if (o < 27) v = m_w[(o - 18) * 576 + c0 * 9 + kk];
            sW[kk * 36 + o] = v;
        }
        __syncthreads();

        #pragma unroll
        for (int c = 0; c < 8; ++c) {
            #pragma unroll
            for (int ki = 0; ki < 3; ++ki) {
                const float* rowp = sX + c * 396 + ki * 132;
                float4 X0 = *(const float4*)&rowp[px4];
                float2 X1 = *(const float2*)&rowp[px4 + 4];
                float xs[6] = {X0.x, X0.y, X0.z, X0.w, X1.x, X1.y};
                int kkb = c * 9 + ki * 3;
                #pragma unroll
                for (int kj = 0; kj < 3; ++kj) {
                    float4 wv = *(const float4*)&sW[(kkb + kj) * 36 + oc];
                    #pragma unroll
                    for (int r = 0; r < 4; ++r) {
                        float a = xs[r + kj];
                        acc[r][0] = fmaf(a, wv.x, acc[r][0]);
                        acc[r][1] = fmaf(a, wv.y, acc[r][1]);
                        acc[r][2] = fmaf(a, wv.z, acc[r][2]);
                        acc[r][3] = fmaf(a, wv.w, acc[r][3]);
                    }
                }
            }
        }
    }

    #pragma unroll
    for (int q = 0; q < 4; ++q) {
        int o = oc + q;
        if (o < 18) {
            float bias = p_b[o];
            float* dst = offs_out + (((size_t)(b * 18 + o)) << 14) + row;
            float4 v = make_float4(acc[0][q] + bias, acc[1][q] + bias,
                                   acc[2][q] + bias, acc[3][q] + bias);
            *(float4*)&dst[px4] = v;
        } else if (o < 27) {
            float bias = m_b[o - 18];
            float* dst = g_mask + (((size_t)(b * 9 + (o - 18))) << 14) + row;
            float4 v;
            v.x = 1.f / (1.f + expf(-(acc[0][q] + bias)));
            v.y = 1.f / (1.f + expf(-(acc[1][q] + bias)));
            v.z = 1.f / (1.f + expf(-(acc[2][q] + bias)));
            v.w = 1.f / (1.f + expf(-(acc[3][q] + bias)));
            *(float4*)&dst[px4] = v;
        }
    }
}

// ---------------------------------------------------------------------------
// Kernel B: modulated deformable conv as tiled SGEMM with smem-window gather.
// Block = one output row (128 px) x 64 oc, 256 threads, K-chunk = 4 input ch.
// A 10-row window of x (rows ~[h-4,h+5]) is staged in smem per chunk; the
// bilinear gather is LDS (near conflict-free: bank = x mod 32) with a rare
// LDG fallback when a tap's corners fall outside the window (flag decided in
// the precompute, so results are exact for any offset magnitude).
// Thread tile 4px x 8oc; balanced lane map (warp = 32px x 32oc).
// ---------------------------------------------------------------------------
#define WROWS 10
__global__ __launch_bounds__(256, 2) void deform_kernel(
    const float* __restrict__ x,
    const float* __restrict__ offs,
    const float* __restrict__ d_w, const float* __restrict__ d_b,
    float* __restrict__ out)
{
    extern __shared__ float smem[];
    float* sA  = smem;                          // 36*128 = 18432 B
    float* sW  = sA + 36 * 128;                 // 36*68  =  9792 B
    float* sX  = sW + 36 * 68;                  // 4*10*128*4 = 20480 B
    float4* swt  = (float4*)(sX + 4 * WROWS * 128); // 9*128*16 = 18432 B
    short4* spos = (short4*)(swt + KKn * Wn);   // 9*128*8 = 9216 B
    unsigned char* sflag = (unsigned char*)(spos + KKn * Wn); // 1152 B

    const int h = blockIdx.x, b = blockIdx.y;
    const int tid = threadIdx.x;
    const int warp = tid >> 5, lane = tid & 31;
    const int px4 = ((warp & 3) * 8 + (lane & 7)) * 4;   // 4 pixels
    const int oc8 = ((warp >> 2) * 4 + (lane >> 3)) * 8; // 8 out channels
    const int row = h * Wn;
    const int ys = min(max(h - 4, 0), Hn - WROWS);       // window start row

    // precompute bilinear corner indices + (mask*validity)-folded weights
    for (int e = tid; e < KKn * Wn; e += 256) {
        int i = e & 127, k = e >> 7;
        float dy = offs[(((size_t)(b * 18 + 2 * k)) << 14) + row + i];
        float dx = offs[(((size_t)(b * 18 + 2 * k + 1)) << 14) + row + i];
        float m  = g_mask[(((size_t)(b * 9 + k)) << 14) + row + i];
        int ki = k / 3, kj = k - ki * 3;
        float py = (float)(h - 1 + ki) + dy;
        float px = (float)(i - 1 + kj) + dx;
        float y0f = floorf(py), x0f = floorf(px);
        float fy = py - y0f, fx = px - x0f;
        int y0 = (int)y0f, x0 = (int)x0f;
        int y1 = y0 + 1, x1 = x0 + 1;
        float vy0 = ((unsigned)y0 < Hn) ? 1.f : 0.f;
        float vy1 = ((unsigned)y1 < Hn) ? 1.f : 0.f;
        float vx0 = ((unsigned)x0 < Wn) ? 1.f : 0.f;
        float vx1 = ((unsigned)x1 < Wn) ? 1.f : 0.f;
        float gy = 1.f - fy, gx = 1.f - fx;
        float4 wq;
        wq.x = gy * gx * m * vy0 * vx0;
        wq.y = gy * fx * m * vy0 * vx1;
        wq.z = fy * gx * m * vy1 * vx0;
        wq.w = fy * fx * m * vy1 * vx1;
        int ry0 = min(max(y0, 0), Hn - 1);
        int ry1 = min(max(y1, 0), Hn - 1);
        int cx0 = min(max(x0, 0), Wn - 1);
        int cx1 = min(max(x1, 0), Wn - 1);
        int inw = (ry0 >= ys) && (ry1 <= ys + WROWS - 1);
        short4 sp;
        if (inw) {
            int r0 = (ry0 - ys) * 128, r1 = (ry1 - ys) * 128;
            sp.x = (short)(r0 + cx0);
            sp.y = (short)(r0 + cx1);
            sp.z = (short)(r1 + cx0);
            sp.w = (short)(r1 + cx1);
        } else {
            sp.x = (short)(ry0 * Wn + cx0);
            sp.y = (short)(ry0 * Wn + cx1);
            sp.z = (short)(ry1 * Wn + cx0);
            sp.w = (short)(ry1 * Wn + cx1);
        }
        spos[e]  = sp;
        swt[e]   = wq;
        sflag[e] = (unsigned char)inw;
    }

    const int px_g = tid & 127;         // gather: this thread's pixel
    const int half = tid >> 7;          // gather: channel half (0/1 -> 2 ch)

    float acc[4][8] = {};

    for (int c0 = 0; c0 < Cn; c0 += 4) {
        __syncthreads();   // prev GEMM done (and spos/swt ready on iter 0)
        // stage weights (36 kk x 64 oc) and the 10-row x window (4 channels)
        #pragma unroll
        for (int j = 0; j < 9; ++j) {
            int e = tid + j * 256;
            int o = e / 36, kk = e - o * 36;
            sW[kk * 68 + o] = d_w[o * 576 + c0 * 9 + kk];
        }
        #pragma unroll
        for (int j = 0; j < 5; ++j) {
            int e = tid + j * 256;          // 0..1279 float4s
            int c = e / 320;                // 320 float4 per channel
            int rem = e - c * 320;          // row*32 + col4
            const float4* src = (const float4*)
                (x + (((size_t)(b * Cn + c0 + c)) << 14) + ys * Wn) + rem;
            ((float4*)sX)[c * 320 + rem] = *src;
        }
        __syncthreads();

        // gather: thread = (pixel, 2-channel half); LDS fast path
        {
            const float* pg = x + (((size_t)(b * Cn + c0 + half * 2)) << 14);
            const float* sx = sX + half * 2 * (WROWS * 128);
            #pragma unroll 3
            for (int t = 0; t < KKn; ++t) {
                short4 sp = spos[t * 128 + px_g];
                float4 w4 = swt[t * 128 + px_g];
                int inw = sflag[t * 128 + px_g];
                int p0 = sp.x, p1 = sp.y, p2 = sp.z, p3 = sp.w;
                if (inw) {
                    #pragma unroll
                    for (int c = 0; c < 2; ++c) {
                        const float* s = sx + c * (WROWS * 128);
                        float v = w4.x * s[p0] + w4.y * s[p1]
                                + w4.z * s[p2] + w4.w * s[p3];
                        sA[((half * 2 + c) * 9 + t) * 128 + px_g] = v;
                    }
                } else {
                    #pragma unroll
                    for (int c = 0; c < 2; ++c) {
                        const float* p = pg + c * HWn;
                        float v = w4.x * __ldg(p + p0) + w4.y * __ldg(p + p1)
                                + w4.z * __ldg(p + p2) + w4.w * __ldg(p + p3);
                        sA[((half * 2 + c) * 9 + t) * 128 + px_g] = v;
                    }
                }
            }
        }
        __syncthreads();

        #pragma unroll 4
        for (int kk = 0; kk < 36; ++kk) {
            float4 av = *(const float4*)&sA[kk * 128 + px4];
            float4 w0 = *(const float4*)&sW[kk * 68 + oc8];
            float4 w1 = *(const float4*)&sW[kk * 68 + oc8 + 4];
            float wv[8] = {w0.x, w0.y, w0.z, w0.w, w1.x, w1.y, w1.z, w1.w};
            float ar[4] = {av.x, av.y, av.z, av.w};
            #pragma unroll
            for (int r = 0; r < 4; ++r)
                #pragma unroll
                for (int q = 0; q < 8; ++q)
                    acc[r][q] = fmaf(ar[r], wv[q], acc[r][q]);
        }
    }

    #pragma unroll
    for (int q = 0; q < 8; ++q) {
        int o = oc8 + q;
        float bias = __ldg(d_b + o);
        float* dst = out + (((size_t)(b * On + o)) << 14) + row;
        float4 v = make_float4(acc[0][q] + bias, acc[1][q] + bias,
                               acc[2][q] + bias, acc[3][q] + bias);
        *(float4*)&dst[px4] = v;
    }
}

// ---------------------------------------------------------------------------

extern "C" void kernel_launch(void* const* d_in, const int* in_sizes, int n_in,
                              void* d_out, int out_size) {
    const float* x    = (const float*)d_in[0];
    const float* p_w  = (const float*)d_in[1];
    const float* p_b  = (const float*)d_in[2];
    const float* m_w  = (const float*)d_in[3];
    const float* m_b  = (const float*)d_in[4];
    const float* d_wp = (const float*)d_in[5];
    const float* d_bp = (const float*)d_in[6];

    float* out = (float*)d_out;                         // [8,64,128,128]
    float* offs_out = out + (size_t)Bn * On * HWn;      // [8,18,128,128]

    const int smemB = (36 * 128 + 36 * 68 + 4 * WROWS * 128) * 4
                    + KKn * Wn * (16 + 8 + 1);          // 77504
    cudaFuncSetAttribute(deform_kernel,
                         cudaFuncAttributeMaxDynamicSharedMemorySize, smemB);

    dim3 grid(Hn, Bn);
    conv_offmask_kernel<<<grid, 256>>>(x, p_w, p_b, m_w, m_b, offs_out);
    deform_kernel<<<grid, 256, smemB>>>(x, offs_out, d_wp, d_bp, out);
}

// round 8
// speedup vs baseline: 1.1527x; 1.0634x over previous
#include <cuda_runtime.h>
#include <math.h>

#define Bn 8
#define Cn 64
#define On 64
#define Hn 128
#define Wn 128
#define HWn 16384
#define KKn 9
#define WR 8            // x-window rows staged in smem

// scratch for sigmoid(mask conv): 8*9*128*128 floats = 4.7MB
__device__ float g_mask[Bn * KKn * HWn];

// ---------------------------------------------------------------------------
// Kernel A: fused 3x3 conv -> 18 offset channels + 9 mask channels (sigmoid).
// (unchanged from best round: ~137us)
// ---------------------------------------------------------------------------
__global__ __launch_bounds__(256) void conv_offmask_kernel(
    const float* __restrict__ x,
    const float* __restrict__ p_w, const float* __restrict__ p_b,
    const float* __restrict__ m_w, const float* __restrict__ m_b,
    float* __restrict__ offs_out)
{
    __shared__ float sX[8 * 3 * 132];   // 12672 B
    __shared__ float sW[72 * 36];       // 10368 B

    const int h = blockIdx.x, b = blockIdx.y;
    const int tid = threadIdx.x;
    const int warp = tid >> 5, lane = tid & 31;
    const int px4 = ((warp & 3) * 8 + (lane & 7)) * 4;
    const int oc  = ((warp >> 2) * 4 + (lane >> 3)) * 4;
    const int row = h * Wn;

    float acc[4][4] = {};

    for (int c0 = 0; c0 < Cn; c0 += 8) {
        __syncthreads();
        for (int e = tid; e < 3168; e += 256) {
            int c = e / 396;
            int rem = e - c * 396;
            int r = rem / 132;
            int i = rem - r * 132;
            int y = h - 1 + r, xc = i - 1;
            float v = 0.f;
            if ((unsigned)y < Hn && (unsigned)xc < Wn)
                v = x[(((size_t)(b * Cn + c0 + c)) << 14) + y * Wn + xc];
            sX[e] = v;
        }
        #pragma unroll 2
        for (int e = tid; e < 72 * 36; e += 256) {
            int o = e / 72, kk = e - o * 72;
            float v = 0.f;
            if (o < 18)      v = p_w[o * 576 + c0 * 9 + kk];
            else if (o < 27) v = m_w[(o - 18) * 576 + c0 * 9 + kk];
            sW[kk * 36 + o] = v;
        }
        __syncthreads();

        #pragma unroll
        for (int c = 0; c < 8; ++c) {
            #pragma unroll
            for (int ki = 0; ki < 3; ++ki) {
                const float* rowp = sX + c * 396 + ki * 132;
                float4 X0 = *(const float4*)&rowp[px4];
                float2 X1 = *(const float2*)&rowp[px4 + 4];
                float xs[6] = {X0.x, X0.y, X0.z, X0.w, X1.x, X1.y};
                int kkb = c * 9 + ki * 3;
                #pragma unroll
                for (int kj = 0; kj < 3; ++kj) {
                    float4 wv = *(const float4*)&sW[(kkb + kj) * 36 + oc];
                    #pragma unroll
                    for (int r = 0; r < 4; ++r) {
                        float a = xs[r + kj];
                        acc[r][0] = fmaf(a, wv.x, acc[r][0]);
                        acc[r][1] = fmaf(a, wv.y, acc[r][1]);
                        acc[r][2] = fmaf(a, wv.z, acc[r][2]);
                        acc[r][3] = fmaf(a, wv.w, acc[r][3]);
                    }
                }
            }
        }
    }

    #pragma unroll
    for (int q = 0; q < 4; ++q) {
        int o = oc + q;
        if (o < 18) {
            float bias = p_b[o];
            float* dst = offs_out + (((size_t)(b * 18 + o)) << 14) + row;
            float4 v = make_float4(acc[0][q] + bias, acc[1][q] + bias,
                                   acc[2][q] + bias, acc[3][q] + bias);
            *(float4*)&dst[px4] = v;
        } else if (o < 27) {
            float bias = m_b[o - 18];
            float* dst = g_mask + (((size_t)(b * 9 + (o - 18))) << 14) + row;
            float4 v;
            v.x = 1.f / (1.f + expf(-(acc[0][q] + bias)));
            v.y = 1.f / (1.f + expf(-(acc[1][q] + bias)));
            v.z = 1.f / (1.f + expf(-(acc[2][q] + bias)));
            v.w = 1.f / (1.f + expf(-(acc[3][q] + bias)));
            *(float4*)&dst[px4] = v;
        }
    }
}

// ---------------------------------------------------------------------------
// Kernel B: modulated deformable conv, tiled SGEMM, conflict-free LDS gather.
// Block = one output row (128px) x 64 oc, 256 threads, K-chunk = 8 input ch.
// 8-row x window in smem; bank = x mod 32 -> gather is conflict-free LDS.
// spos = single short p0, corners at p0+{0,1,128,129}; zero folded weights
// make all stray in-smem reads exact. Rare out-of-window taps take a
// per-warp-uniform global fallback (__all_sync).
// ---------------------------------------------------------------------------
__global__ __launch_bounds__(256, 2) void deform_kernel(
    const float* __restrict__ x,
    const float* __restrict__ offs,
    const float* __restrict__ d_w, const float* __restrict__ d_b,
    float* __restrict__ out)
{
    extern __shared__ float smem[];
    float*  sA    = smem;                            // 72*128 f   (36864 B)
    float*  sW    = sA + 72 * 128;                   // 72*68 f    (19584 B)
    short*  spos  = (short*)(sW + 72 * 68);          // 1152 short (2304 B)
    unsigned char* sflag = (unsigned char*)(spos + KKn * Wn);  // 1152 B
    float4* swt   = (float4*)((char*)smem + 59904);  // 9*128 f4   (18432 B)
    float*  sX    = (float*)((char*)smem + 78336);   // 8ch*8r*128 (32768 B)
    float*  guard = sX + 8 * WR * Wn;                // 258 f      (1032 B)

    const int h = blockIdx.x, b = blockIdx.y;
    const int tid = threadIdx.x;
    const int warp = tid >> 5, lane = tid & 31;
    const int px4 = ((warp & 3) * 8 + (lane & 7)) * 4;   // 4 pixels
    const int oc8 = ((warp >> 2) * 4 + (lane >> 3)) * 8; // 8 out channels
    const int row = h * Wn;
    const int ys = min(max(h - 3, 0), Hn - WR);          // window start row

    // zero the guard (stray fast-path reads for the last channel land here)
    for (int e = tid; e < 258; e += 256) guard[e] = 0.f;

    // precompute: folded bilinear weights + window-relative base index + flag
    for (int e = tid; e < KKn * Wn; e += 256) {
        int i = e & 127, k = e >> 7;
        float dy = offs[(((size_t)(b * 18 + 2 * k)) << 14) + row + i];
        float dx = offs[(((size_t)(b * 18 + 2 * k + 1)) << 14) + row + i];
        float m  = g_mask[(((size_t)(b * 9 + k)) << 14) + row + i];
        int ki = k / 3, kj = k - ki * 3;
        float py = (float)(h - 1 + ki) + dy;
        float px = (float)(i - 1 + kj) + dx;
        float y0f = floorf(py), x0f = floorf(px);
        float fy = py - y0f, fx = px - x0f;
        int y0 = (int)y0f, x0 = (int)x0f;
        int y1 = y0 + 1, x1 = x0 + 1;
        float vy0 = ((unsigned)y0 < Hn) ? 1.f : 0.f;
        float vy1 = ((unsigned)y1 < Hn) ? 1.f : 0.f;
        float vx0 = ((unsigned)x0 < Wn) ? 1.f : 0.f;
        float vx1 = ((unsigned)x1 < Wn) ? 1.f : 0.f;
        float gy = 1.f - fy, gx = 1.f - fx;
        float4 wq;
        wq.x = gy * gx * m * vy0 * vx0;
        wq.y = gy * fx * m * vy0 * vx1;
        wq.z = fy * gx * m * vy1 * vx0;
        wq.w = fy * fx * m * vy1 * vx1;
        // fast iff every nonzero-weight corner row lies inside the window
        int f0 = (y0 < 0) | (y0 > Hn - 1) | ((y0 >= ys) & (y0 <= ys + WR - 1));
        int f1 = (y1 < 0) | (y1 > Hn - 1) | ((y1 >= ys) & (y1 <= ys + WR - 1));
        int rr = min(max(y0 - ys, -1), WR);       // garbage-safe clamp
        int xb = min(max(x0, -1), Wn);
        spos[e]  = (short)(rr * Wn + xb);
        swt[e]   = wq;
        sflag[e] = (unsigned char)(f0 & f1);
    }

    const int px_g = tid & 127;         // gather: this thread's pixel
    const int half = tid >> 7;          // gather: channel half (0/1 -> 4 ch)

    float acc[4][8] = {};

    for (int c0 = 0; c0 < Cn; c0 += 8) {
        __syncthreads();   // prev GEMM done (and precompute done on iter 0)
        // weight stage (72 kk x 64 oc)
        #pragma unroll
        for (int j = 0; j < 18; ++j) {
            int e = tid + j * 256;
            int o = e / 72, kk = e - o * 72;
            sW[kk * 68 + o] = d_w[o * 576 + c0 * 9 + kk];
        }
        // stage 8-row window for 8 channels (2048 float4)
        #pragma unroll
        for (int j = 0; j < 8; ++j) {
            int e = tid + j * 256;          // float4 index
            int c = e >> 8;                 // 256 f4 per channel
            int rem = e & 255;
            const float4* src = (const float4*)
                (x + (((size_t)(b * Cn + c0 + c)) << 14) + ys * Wn) + rem;
            ((float4*)sX)[(c << 8) + rem] = *src;
        }
        __syncthreads();

        // gather: thread = (pixel, 4-channel half); conflict-free LDS
        {
            const float* sxc = sX + half * 4 * (WR * Wn);
            const float* pg  = x + (((size_t)(b * Cn + c0 + half * 4)) << 14);
            #pragma unroll
            for (int t = 0; t < KKn; ++t) {
                int   p0 = spos[t * 128 + px_g];
                float4 w4 = swt[t * 128 + px_g];
                int fast = sflag[t * 128 + px_g];
                if (__all_sync(0xffffffffu, fast)) {
                    #pragma unroll
                    for (int c = 0; c < 4; ++c) {
                        const float* s = sxc + c * (WR * Wn);
                        float v = w4.x * s[p0]       + w4.y * s[p0 + 1]
                                + w4.z * s[p0 + 128] + w4.w * s[p0 + 129];
                        sA[((half * 4 + c) * 9 + t) * 128 + px_g] = v;
                    }
                } else {
                    // exact slow path: recompute global clamped corners
                    float dy = offs[(((size_t)(b * 18 + 2 * t)) << 14) + row + px_g];
                    float dx = offs[(((size_t)(b * 18 + 2 * t + 1)) << 14) + row + px_g];
                    int ki = t / 3, kj = t - ki * 3;
                    float py = (float)(h - 1 + ki) + dy;
                    float px = (float)(px_g - 1 + kj) + dx;
                    int y0 = (int)floorf(py), x0 = (int)floorf(px);
                    int ry0 = min(max(y0, 0), Hn - 1) * Wn;
                    int ry1 = min(max(y0 + 1, 0), Hn - 1) * Wn;
                    int cx0 = min(max(x0, 0), Wn - 1);
                    int cx1 = min(max(x0 + 1, 0), Wn - 1);
                    int q0 = ry0 + cx0, q1 = ry0 + cx1;
                    int q2 = ry1 + cx0, q3 = ry1 + cx1;
                    #pragma unroll
                    for (int c = 0; c < 4; ++c) {
                        const float* p = pg + c * HWn;
                        float v = w4.x * __ldg(p + q0) + w4.y * __ldg(p + q1)
                                + w4.z * __ldg(p + q2) + w4.w * __ldg(p + q3);
                        sA[((half * 4 + c) * 9 + t) * 128 + px_g] = v;
                    }
                }
            }
        }
        __syncthreads();

        #pragma unroll 4
        for (int kk = 0; kk < 72; ++kk) {
            float4 av = *(const float4*)&sA[kk * 128 + px4];
            float4 w0 = *(const float4*)&sW[kk * 68 + oc8];
            float4 w1 = *(const float4*)&sW[kk * 68 + oc8 + 4];
            float wv[8] = {w0.x, w0.y, w0.z, w0.w, w1.x, w1.y, w1.z, w1.w};
            float ar[4] = {av.x, av.y, av.z, av.w};
            #pragma unroll
            for (int r = 0; r < 4; ++r)
                #pragma unroll
                for (int q = 0; q < 8; ++q)
                    acc[r][q] = fmaf(ar[r], wv[q], acc[r][q]);
        }
    }

    #pragma unroll
    for (int q = 0; q < 8; ++q) {
        int o = oc8 + q;
        float bias = __ldg(d_b + o);
        float* dst = out + (((size_t)(b * On + o)) << 14) + row;
        float4 v = make_float4(acc[0][q] + bias, acc[1][q] + bias,
                               acc[2][q] + bias, acc[3][q] + bias);
        *(float4*)&dst[px4] = v;
    }
}

// ---------------------------------------------------------------------------

extern "C" void kernel_launch(void* const* d_in, const int* in_sizes, int n_in,
                              void* d_out, int out_size) {
    const float* x    = (const float*)d_in[0];
    const float* p_w  = (const float*)d_in[1];
    const float* p_b  = (const float*)d_in[2];
    const float* m_w  = (const float*)d_in[3];
    const float* m_b  = (const float*)d_in[4];
    const float* d_wp = (const float*)d_in[5];
    const float* d_bp = (const float*)d_in[6];

    float* out = (float*)d_out;                         // [8,64,128,128]
    float* offs_out = out + (size_t)Bn * On * HWn;      // [8,18,128,128]

    // layout: sA(36864) sW(19584) spos(2304) sflag(1152+pad) | swt@59904
    //         (18432) | sX@78336 (32768) | guard (1032)
    const int smemB = 78336 + 8 * WR * Wn * 4 + 258 * 4;   // 112136
    cudaFuncSetAttribute(deform_kernel,
                         cudaFuncAttributeMaxDynamicSharedMemorySize, smemB);

    dim3 grid(Hn, Bn);
    conv_offmask_kernel<<<grid, 256>>>(x, p_w, p_b, m_w, m_b, offs_out);
    deform_kernel<<<grid, 256, smemB>>>(x, offs_out, d_wp, d_bp, out);
}

// round 9
// speedup vs baseline: 1.2357x; 1.0720x over previous
#include <cuda_runtime.h>
#include <math.h>

#define Bn 8
#define Cn 64
#define On 64
#define Hn 128
#define Wn 128
#define HWn 16384
#define KKn 9
#define WR 8            // x-window rows staged in smem

typedef unsigned long long u64;

// packed dual-fp32 FMA: (lo,hi) elementwise, exact fp32 semantics
__device__ __forceinline__ u64 fma2(u64 a, u64 b, u64 c) {
    u64 d;
    asm("fma.rn.f32x2 %0,%1,%2,%3;" : "=l"(d) : "l"(a), "l"(b), "l"(c));
    return d;
}
__device__ __forceinline__ u64 dup2(float a) {
    u64 d;
    asm("mov.b64 %0,{%1,%1};" : "=l"(d) : "f"(a));
    return d;
}
__device__ __forceinline__ void unpack2(u64 v, float& lo, float& hi) {
    asm("mov.b64 {%0,%1},%2;" : "=f"(lo), "=f"(hi) : "l"(v));
}

// scratch for sigmoid(mask conv): 8*9*128*128 floats = 4.7MB
__device__ float g_mask[Bn * KKn * HWn];

// ---------------------------------------------------------------------------
// Kernel A: fused 3x3 conv -> 18 offset channels + 9 mask channels (sigmoid).
// GEMM inner loop on fma.rn.f32x2 (oc-pairs packed).
// ---------------------------------------------------------------------------
__global__ __launch_bounds__(256) void conv_offmask_kernel(
    const float* __restrict__ x,
    const float* __restrict__ p_w, const float* __restrict__ p_b,
    const float* __restrict__ m_w, const float* __restrict__ m_b,
    float* __restrict__ offs_out)
{
    __shared__ float sX[8 * 3 * 132];   // 12672 B
    __shared__ float sW[72 * 36];       // 10368 B

    const int h = blockIdx.x, b = blockIdx.y;
    const int tid = threadIdx.x;
    const int warp = tid >> 5, lane = tid & 31;
    const int px4 = ((warp & 3) * 8 + (lane & 7)) * 4;
    const int oc  = ((warp >> 2) * 4 + (lane >> 3)) * 4;
    const int row = h * Wn;

    u64 acc2[4][2] = {};        // [px][oc-pair], each u64 = 2 packed fp32

    for (int c0 = 0; c0 < Cn; c0 += 8) {
        __syncthreads();
        for (int e = tid; e < 3168; e += 256) {
            int c = e / 396;
            int rem = e - c * 396;
            int r = rem / 132;
            int i = rem - r * 132;
            int y = h - 1 + r, xc = i - 1;
            float v = 0.f;
            if ((unsigned)y < Hn && (unsigned)xc < Wn)
                v = x[(((size_t)(b * Cn + c0 + c)) << 14) + y * Wn + xc];
            sX[e] = v;
        }
        #pragma unroll 2
        for (int e = tid; e < 72 * 36; e += 256) {
            int o = e / 72, kk = e - o * 72;
            float v = 0.f;
            if (o < 18)      v = p_w[o * 576 + c0 * 9 + kk];
            else if (o < 27) v = m_w[(o - 18) * 576 + c0 * 9 + kk];
            sW[kk * 36 + o] = v;
        }
        __syncthreads();

        #pragma unroll
        for (int c = 0; c < 8; ++c) {
            #pragma unroll
            for (int ki = 0; ki < 3; ++ki) {
                const float* rowp = sX + c * 396 + ki * 132;
                float4 X0 = *(const float4*)&rowp[px4];
                float2 X1 = *(const float2*)&rowp[px4 + 4];
                float xs[6] = {X0.x, X0.y, X0.z, X0.w, X1.x, X1.y};
                int kkb = c * 9 + ki * 3;
                #pragma unroll
                for (int kj = 0; kj < 3; ++kj) {
                    float4 wv = *(const float4*)&sW[(kkb + kj) * 36 + oc];
                    u64 wp0 = ((const u64*)&wv)[0];
                    u64 wp1 = ((const u64*)&wv)[1];
                    #pragma unroll
                    for (int r = 0; r < 4; ++r) {
                        u64 ar = dup2(xs[r + kj]);
                        acc2[r][0] = fma2(ar, wp0, acc2[r][0]);
                        acc2[r][1] = fma2(ar, wp1, acc2[r][1]);
                    }
                }
            }
        }
    }

    float acc[4][4];
    #pragma unroll
    for (int r = 0; r < 4; ++r) {
        unpack2(acc2[r][0], acc[r][0], acc[r][1]);
        unpack2(acc2[r][1], acc[r][2], acc[r][3]);
    }

    #pragma unroll
    for (int q = 0; q < 4; ++q) {
        int o = oc + q;
        if (o < 18) {
            float bias = p_b[o];
            float* dst = offs_out + (((size_t)(b * 18 + o)) << 14) + row;
            float4 v = make_float4(acc[0][q] + bias, acc[1][q] + bias,
                                   acc[2][q] + bias, acc[3][q] + bias);
            *(float4*)&dst[px4] = v;
        } else if (o < 27) {
            float bias = m_b[o - 18];
            float* dst = g_mask + (((size_t)(b * 9 + (o - 18))) << 14) + row;
            float4 v;
            v.x = 1.f / (1.f + expf(-(acc[0][q] + bias)));
            v.y = 1.f / (1.f + expf(-(acc[1][q] + bias)));
            v.z = 1.f / (1.f + expf(-(acc[2][q] + bias)));
            v.w = 1.f / (1.f + expf(-(acc[3][q] + bias)));
            *(float4*)&dst[px4] = v;
        }
    }
}

// ---------------------------------------------------------------------------
// Kernel B: modulated deformable conv, tiled SGEMM, conflict-free LDS gather,
// GEMM inner loop on fma.rn.f32x2 (oc-pairs packed).
// ---------------------------------------------------------------------------
__global__ __launch_bounds__(256, 2) void deform_kernel(
    const float* __restrict__ x,
    const float* __restrict__ offs,
    const float* __restrict__ d_w, const float* __restrict__ d_b,
    float* __restrict__ out)
{
    extern __shared__ float smem[];
    float*  sA    = smem;                            // 72*128 f   (36864 B)
    float*  sW    = sA + 72 * 128;                   // 72*68 f    (19584 B)
    short*  spos  = (short*)(sW + 72 * 68);          // 1152 short (2304 B)
    unsigned char* sflag = (unsigned char*)(spos + KKn * Wn);  // 1152 B
    float4* swt   = (float4*)((char*)smem + 59904);  // 9*128 f4   (18432 B)
    float*  sX    = (float*)((char*)smem + 78336);   // 8ch*8r*128 (32768 B)
    float*  guard = sX + 8 * WR * Wn;                // 258 f      (1032 B)

    const int h = blockIdx.x, b = blockIdx.y;
    const int tid = threadIdx.x;
    const int warp = tid >> 5, lane = tid & 31;
    const int px4 = ((warp & 3) * 8 + (lane & 7)) * 4;   // 4 pixels
    const int oc8 = ((warp >> 2) * 4 + (lane >> 3)) * 8; // 8 out channels
    const int row = h * Wn;
    const int ys = min(max(h - 3, 0), Hn - WR);          // window start row

    for (int e = tid; e < 258; e += 256) guard[e] = 0.f;

    // precompute: folded bilinear weights + window-relative base index + flag
    for (int e = tid; e < KKn * Wn; e += 256) {
        int i = e & 127, k = e >> 7;
        float dy = offs[(((size_t)(b * 18 + 2 * k)) << 14) + row + i];
        float dx = offs[(((size_t)(b * 18 + 2 * k + 1)) << 14) + row + i];
        float m  = g_mask[(((size_t)(b * 9 + k)) << 14) + row + i];
        int ki = k / 3, kj = k - ki * 3;
        float py = (float)(h - 1 + ki) + dy;
        float px = (float)(i - 1 + kj) + dx;
        float y0f = floorf(py), x0f = floorf(px);
        float fy = py - y0f, fx = px - x0f;
        int y0 = (int)y0f, x0 = (int)x0f;
        int y1 = y0 + 1, x1 = x0 + 1;
        float vy0 = ((unsigned)y0 < Hn) ? 1.f : 0.f;
        float vy1 = ((unsigned)y1 < Hn) ? 1.f : 0.f;
        float vx0 = ((unsigned)x0 < Wn) ? 1.f : 0.f;
        float vx1 = ((unsigned)x1 < Wn) ? 1.f : 0.f;
        float gy = 1.f - fy, gx = 1.f - fx;
        float4 wq;
        wq.x = gy * gx * m * vy0 * vx0;
        wq.y = gy * fx * m * vy0 * vx1;
        wq.z = fy * gx * m * vy1 * vx0;
        wq.w = fy * fx * m * vy1 * vx1;
        int f0 = (y0 < 0) | (y0 > Hn - 1) | ((y0 >= ys) & (y0 <= ys + WR - 1));
        int f1 = (y1 < 0) | (y1 > Hn - 1) | ((y1 >= ys) & (y1 <= ys + WR - 1));
        int rr = min(max(y0 - ys, -1), WR);       // garbage-safe clamp
        int xb = min(max(x0, -1), Wn);
        spos[e]  = (short)(rr * Wn + xb);
        swt[e]   = wq;
        sflag[e] = (unsigned char)(f0 & f1);
    }

    const int px_g = tid & 127;         // gather: this thread's pixel
    const int half = tid >> 7;          // gather: channel half (0/1 -> 4 ch)

    u64 acc2[4][4] = {};                // [px][oc-pair]

    for (int c0 = 0; c0 < Cn; c0 += 8) {
        __syncthreads();   // prev GEMM done (and precompute done on iter 0)
        #pragma unroll
        for (int j = 0; j < 18; ++j) {
            int e = tid + j * 256;
            int o = e / 72, kk = e - o * 72;
            sW[kk * 68 + o] = d_w[o * 576 + c0 * 9 + kk];
        }
        #pragma unroll
        for (int j = 0; j < 8; ++j) {
            int e = tid + j * 256;          // float4 index
            int c = e >> 8;                 // 256 f4 per channel
            int rem = e & 255;
            const float4* src = (const float4*)
                (x + (((size_t)(b * Cn + c0 + c)) << 14) + ys * Wn) + rem;
            ((float4*)sX)[(c << 8) + rem] = *src;
        }
        __syncthreads();

        // gather: thread = (pixel, 4-channel half); conflict-free LDS
        {
            const float* sxc = sX + half * 4 * (WR * Wn);
            const float* pg  = x + (((size_t)(b * Cn + c0 + half * 4)) << 14);
            #pragma unroll
            for (int t = 0; t < KKn; ++t) {
                int   p0 = spos[t * 128 + px_g];
                float4 w4 = swt[t * 128 + px_g];
                int fast = sflag[t * 128 + px_g];
                if (__all_sync(0xffffffffu, fast)) {
                    #pragma unroll
                    for (int c = 0; c < 4; ++c) {
                        const float* s = sxc + c * (WR * Wn);
                        float v = w4.x * s[p0]       + w4.y * s[p0 + 1]
                                + w4.z * s[p0 + 128] + w4.w * s[p0 + 129];
                        sA[((half * 4 + c) * 9 + t) * 128 + px_g] = v;
                    }
                } else {
                    float dy = offs[(((size_t)(b * 18 + 2 * t)) << 14) + row + px_g];
                    float dx = offs[(((size_t)(b * 18 + 2 * t + 1)) << 14) + row + px_g];
                    int ki = t / 3, kj = t - ki * 3;
                    float py = (float)(h - 1 + ki) + dy;
                    float px = (float)(px_g - 1 + kj) + dx;
                    int y0 = (int)floorf(py), x0 = (int)floorf(px);
                    int ry0 = min(max(y0, 0), Hn - 1) * Wn;
                    int ry1 = min(max(y0 + 1, 0), Hn - 1) * Wn;
                    int cx0 = min(max(x0, 0), Wn - 1);
                    int cx1 = min(max(x0 + 1, 0), Wn - 1);
                    int q0 = ry0 + cx0, q1 = ry0 + cx1;
                    int q2 = ry1 + cx0, q3 = ry1 + cx1;
                    #pragma unroll
                    for (int c = 0; c < 4; ++c) {
                        const float* p = pg + c * HWn;
                        float v = w4.x * __ldg(p + q0) + w4.y * __ldg(p + q1)
                                + w4.z * __ldg(p + q2) + w4.w * __ldg(p + q3);
                        sA[((half * 4 + c) * 9 + t) * 128 + px_g] = v;
                    }
                }
            }
        }
        __syncthreads();

        #pragma unroll 4
        for (int kk = 0; kk < 72; ++kk) {
            float4 av = *(const float4*)&sA[kk * 128 + px4];
            float4 w0 = *(const float4*)&sW[kk * 68 + oc8];
            float4 w1 = *(const float4*)&sW[kk * 68 + oc8 + 4];
            u64 wp[4] = {((const u64*)&w0)[0], ((const u64*)&w0)[1],
                         ((const u64*)&w1)[0], ((const u64*)&w1)[1]};
            float ar[4] = {av.x, av.y, av.z, av.w};
            #pragma unroll
            for (int r = 0; r < 4; ++r) {
                u64 ad = dup2(ar[r]);
                #pragma unroll
                for (int p = 0; p < 4; ++p)
                    acc2[r][p] = fma2(ad, wp[p], acc2[r][p]);
            }
        }
    }

    float acc[4][8];
    #pragma unroll
    for (int r = 0; r < 4; ++r)
        #pragma unroll
        for (int p = 0; p < 4; ++p)
            unpack2(acc2[r][p], acc[r][2 * p], acc[r][2 * p + 1]);

    #pragma unroll
    for (int q = 0; q < 8; ++q) {
        int o = oc8 + q;
        float bias = __ldg(d_b + o);
        float* dst = out + (((size_t)(b * On + o)) << 14) + row;
        float4 v = make_float4(acc[0][q] + bias, acc[1][q] + bias,
                               acc[2][q] + bias, acc[3][q] + bias);
        *(float4*)&dst[px4] = v;
    }
}

// ---------------------------------------------------------------------------

extern "C" void kernel_launch(void* const* d_in, const int* in_sizes, int n_in,
                              void* d_out, int out_size) {
    const float* x    = (const float*)d_in[0];
    const float* p_w  = (const float*)d_in[1];
    const float* p_b  = (const float*)d_in[2];
    const float* m_w  = (const float*)d_in[3];
    const float* m_b  = (const float*)d_in[4];
    const float* d_wp = (const float*)d_in[5];
    const float* d_bp = (const float*)d_in[6];

    float* out = (float*)d_out;                         // [8,64,128,128]
    float* offs_out = out + (size_t)Bn * On * HWn;      // [8,18,128,128]

    const int smemB = 78336 + 8 * WR * Wn * 4 + 258 * 4;   // 112136
    cudaFuncSetAttribute(deform_kernel,
                         cudaFuncAttributeMaxDynamicSharedMemorySize, smemB);

    dim3 grid(Hn, Bn);
    conv_offmask_kernel<<<grid, 256>>>(x, p_w, p_b, m_w, m_b, offs_out);
    deform_kernel<<<grid, 256, smemB>>>(x, offs_out, d_wp, d_bp, out);
}

// round 10
// speedup vs baseline: 1.2475x; 1.0095x over previous
#include <cuda_runtime.h>
#include <math.h>

#define Bn 8
#define Cn 64
#define On 64
#define Hn 128
#define Wn 128
#define HWn 16384
#define KKn 9
#define WR 8            // x-window rows staged in smem (kernel B)

typedef unsigned long long u64;

// packed dual-fp32 FMA: (lo,hi) elementwise, exact fp32 semantics
__device__ __forceinline__ u64 fma2(u64 a, u64 b, u64 c) {
    u64 d;
    asm("fma.rn.f32x2 %0,%1,%2,%3;" : "=l"(d) : "l"(a), "l"(b), "l"(c));
    return d;
}
__device__ __forceinline__ u64 dup2(float a) {
    u64 d;
    asm("mov.b64 %0,{%1,%1};" : "=l"(d) : "f"(a));
    return d;
}
__device__ __forceinline__ void unpack2(u64 v, float& lo, float& hi) {
    asm("mov.b64 {%0,%1},%2;" : "=f"(lo), "=f"(hi) : "l"(v));
}

// scratch for sigmoid(mask conv): 8*9*128*128 floats = 4.7MB
__device__ float g_mask[Bn * KKn * HWn];

// ---------------------------------------------------------------------------
// Kernel A: fused 3x3 conv -> 18 offset + 9 mask (sigmoid) channels.
// Block = TWO output rows (2*h2, 2*h2+1) of one batch, 256 threads.
// Stages 4 raw x-rows x 8 ch per chunk with pure aligned float4 stores
// (no div/mod); halo slots are compile-time zero (conv padding). GEMM on
// fma.rn.f32x2, thread tile = 2 rows x 4 px x 4 oc.
// ---------------------------------------------------------------------------
__global__ __launch_bounds__(256) void conv_offmask_kernel(
    const float* __restrict__ x,
    const float* __restrict__ p_w, const float* __restrict__ p_b,
    const float* __restrict__ m_w, const float* __restrict__ m_b,
    float* __restrict__ offs_out)
{
    __shared__ float sX[8][4][132];     // 16896 B  (cols 0..127; 128..131 = 0)
    __shared__ float sW[72 * 36];       // 10368 B

    const int h2 = blockIdx.x, b = blockIdx.y;   // rows 2*h2, 2*h2+1
    const int tid = threadIdx.x;
    const int warp = tid >> 5, lane = tid & 31;
    const int px4 = ((warp & 3) * 8 + (lane & 7)) * 4;   // 4 pixels
    const int oc  = ((warp >> 2) * 4 + (lane >> 3)) * 4; // 4 out channels
    const int i0  = px4 ? (px4 - 1) : 130;               // col px4-1 (130 = 0)

    // zero the halo tail once (cols 128..131 of every staged row)
    if (tid < 128) {
        int c = tid >> 4, r = (tid >> 2) & 3, k = tid & 3;
        sX[c][r][128 + k] = 0.f;
    }

    u64 acc2[2][4][2] = {};   // [row][px][oc-pair]

    for (int c0 = 0; c0 < Cn; c0 += 8) {
        __syncthreads();
        // stage 4 rows x 8 ch, cols 0..127, aligned float4 (4 iterations)
        #pragma unroll
        for (int j = 0; j < 4; ++j) {
            int e = tid + j * 256;
            int cr = e >> 5, q = e & 31;
            int c = cr >> 2, r = cr & 3;
            int y = 2 * h2 - 1 + r;
            float4 v = make_float4(0.f, 0.f, 0.f, 0.f);
            if ((unsigned)y < Hn)
                v = *(const float4*)
                    (x + (((size_t)(b * Cn + c0 + c)) << 14) + y * Wn + q * 4);
            *(float4*)&sX[c][r][q * 4] = v;
        }
        // stage weights for this chunk: sW[kk_local][o], o padded to 36
        #pragma unroll 2
        for (int e = tid; e < 72 * 36; e += 256) {
            int o = e / 72, kk = e - o * 72;
            float v = 0.f;
            if (o < 18)      v = p_w[o * 576 + c0 * 9 + kk];
            else if (o < 27) v = m_w[(o - 18) * 576 + c0 * 9 + kk];
            sW[kk * 36 + o] = v;
        }
        __syncthreads();

        #pragma unroll
        for (int c = 0; c < 8; ++c) {
            #pragma unroll
            for (int ki = 0; ki < 3; ++ki) {
                const float* r0 = sX[c][ki];       // input row for out-row 0
                const float* r1 = sX[c][ki + 1];   // input row for out-row 1
                float4 Xa = *(const float4*)&r0[px4];
                float4 Xb = *(const float4*)&r1[px4];
                float xsA[6] = {r0[i0], Xa.x, Xa.y, Xa.z, Xa.w, r0[px4 + 4]};
                float xsB[6] = {r1[i0], Xb.x, Xb.y, Xb.z, Xb.w, r1[px4 + 4]};
                int kkb = c * 9 + ki * 3;
                #pragma unroll
                for (int kj = 0; kj < 3; ++kj) {
                    float4 wv = *(const float4*)&sW[(kkb + kj) * 36 + oc];
                    u64 wp0 = ((const u64*)&wv)[0];
                    u64 wp1 = ((const u64*)&wv)[1];
                    #pragma unroll
                    for (int r = 0; r < 4; ++r) {
                        u64 aA = dup2(xsA[r + kj]);
                        acc2[0][r][0] = fma2(aA, wp0, acc2[0][r][0]);
                        acc2[0][r][1] = fma2(aA, wp1, acc2[0][r][1]);
                        u64 aB = dup2(xsB[r + kj]);
                        acc2[1][r][0] = fma2(aB, wp0, acc2[1][r][0]);
                        acc2[1][r][1] = fma2(aB, wp1, acc2[1][r][1]);
                    }
                }
            }
        }
    }

    #pragma unroll
    for (int rr = 0; rr < 2; ++rr) {
        int row = (2 * h2 + rr) * Wn;
        float acc[4][4];
        #pragma unroll
        for (int r = 0; r < 4; ++r) {
            unpack2(acc2[rr][r][0], acc[r][0], acc[r][1]);
            unpack2(acc2[rr][r][1], acc[r][2], acc[r][3]);
        }
        #pragma unroll
        for (int q = 0; q < 4; ++q) {
            int o = oc + q;
            if (o < 18) {
                float bias = p_b[o];
                float* dst = offs_out + (((size_t)(b * 18 + o)) << 14) + row;
                float4 v = make_float4(acc[0][q] + bias, acc[1][q] + bias,
                                       acc[2][q] + bias, acc[3][q] + bias);
                *(float4*)&dst[px4] = v;
            } else if (o < 27) {
                float bias = m_b[o - 18];
                float* dst = g_mask + (((size_t)(b * 9 + (o - 18))) << 14) + row;
                float4 v;
                v.x = 1.f / (1.f + expf(-(acc[0][q] + bias)));
                v.y = 1.f / (1.f + expf(-(acc[1][q] + bias)));
                v.z = 1.f / (1.f + expf(-(acc[2][q] + bias)));
                v.w = 1.f / (1.f + expf(-(acc[3][q] + bias)));
                *(float4*)&dst[px4] = v;
            }
        }
    }
}

// ---------------------------------------------------------------------------
// Kernel B: modulated deformable conv, tiled SGEMM, conflict-free LDS gather,
// GEMM inner loop on fma.rn.f32x2 (oc-pairs packed). (unchanged from R9)
// ---------------------------------------------------------------------------
__global__ __launch_bounds__(256, 2) void deform_kernel(
    const float* __restrict__ x,
    const float* __restrict__ offs,
    const float* __restrict__ d_w, const float* __restrict__ d_b,
    float* __restrict__ out)
{
    extern __shared__ float smem[];
    float*  sA    = smem;                            // 72*128 f   (36864 B)
    float*  sW    = sA + 72 * 128;                   // 72*68 f    (19584 B)
    short*  spos  = (short*)(sW + 72 * 68);          // 1152 short (2304 B)
    unsigned char* sflag = (unsigned char*)(spos + KKn * Wn);  // 1152 B
    float4* swt   = (float4*)((char*)smem + 59904);  // 9*128 f4   (18432 B)
    float*  sX    = (float*)((char*)smem + 78336);   // 8ch*8r*128 (32768 B)
    float*  guard = sX + 8 * WR * Wn;                // 258 f      (1032 B)

    const int h = blockIdx.x, b = blockIdx.y;
    const int tid = threadIdx.x;
    const int warp = tid >> 5, lane = tid & 31;
    const int px4 = ((warp & 3) * 8 + (lane & 7)) * 4;   // 4 pixels
    const int oc8 = ((warp >> 2) * 4 + (lane >> 3)) * 8; // 8 out channels
    const int row = h * Wn;
    const int ys = min(max(h - 3, 0), Hn - WR);          // window start row

    for (int e = tid; e < 258; e += 256) guard[e] = 0.f;

    // precompute: folded bilinear weights + window-relative base index + flag
    for (int e = tid; e < KKn * Wn; e += 256) {
        int i = e & 127, k = e >> 7;
        float dy = offs[(((size_t)(b * 18 + 2 * k)) << 14) + row + i];
        float dx = offs[(((size_t)(b * 18 + 2 * k + 1)) << 14) + row + i];
        float m  = g_mask[(((size_t)(b * 9 + k)) << 14) + row + i];
        int ki = k / 3, kj = k - ki * 3;
        float py = (float)(h - 1 + ki) + dy;
        float px = (float)(i - 1 + kj) + dx;
        float y0f = floorf(py), x0f = floorf(px);
        float fy = py - y0f, fx = px - x0f;
        int y0 = (int)y0f, x0 = (int)x0f;
        int y1 = y0 + 1, x1 = x0 + 1;
        float vy0 = ((unsigned)y0 < Hn) ? 1.f : 0.f;
        float vy1 = ((unsigned)y1 < Hn) ? 1.f : 0.f;
        float vx0 = ((unsigned)x0 < Wn) ? 1.f : 0.f;
        float vx1 = ((unsigned)x1 < Wn) ? 1.f : 0.f;
        float gy = 1.f - fy, gx = 1.f - fx;
        float4 wq;
        wq.x = gy * gx * m * vy0 * vx0;
        wq.y = gy * fx * m * vy0 * vx1;
        wq.z = fy * gx * m * vy1 * vx0;
        wq.w = fy * fx * m * vy1 * vx1;
        int f0 = (y0 < 0) | (y0 > Hn - 1) | ((y0 >= ys) & (y0 <= ys + WR - 1));
        int f1 = (y1 < 0) | (y1 > Hn - 1) | ((y1 >= ys) & (y1 <= ys + WR - 1));
        int rr = min(max(y0 - ys, -1), WR);       // garbage-safe clamp
        int xb = min(max(x0, -1), Wn);
        spos[e]  = (short)(rr * Wn + xb);
        swt[e]   = wq;
        sflag[e] = (unsigned char)(f0 & f1);
    }

    const int px_g = tid & 127;         // gather: this thread's pixel
    const int half = tid >> 7;          // gather: channel half (0/1 -> 4 ch)

    u64 acc2[4][4] = {};                // [px][oc-pair]

    for (int c0 = 0; c0 < Cn; c0 += 8) {
        __syncthreads();   // prev GEMM done (and precompute done on iter 0)
        #pragma unroll
        for (int j = 0; j < 18; ++j) {
            int e = tid + j * 256;
            int o = e / 72, kk = e - o * 72;
            sW[kk * 68 + o] = d_w[o * 576 + c0 * 9 + kk];
        }
        #pragma unroll
        for (int j = 0; j < 8; ++j) {
            int e = tid + j * 256;          // float4 index
            int c = e >> 8;                 // 256 f4 per channel
            int rem = e & 255;
            const float4* src = (const float4*)
                (x + (((size_t)(b * Cn + c0 + c)) << 14) + ys * Wn) + rem;
            ((float4*)sX)[(c << 8) + rem] = *src;
        }
        __syncthreads();

        // gather: thread = (pixel, 4-channel half); conflict-free LDS
        {
            const float* sxc = sX + half * 4 * (WR * Wn);
            const float* pg  = x + (((size_t)(b * Cn + c0 + half * 4)) << 14);
            #pragma unroll
            for (int t = 0; t < KKn; ++t) {
                int   p0 = spos[t * 128 + px_g];
                float4 w4 = swt[t * 128 + px_g];
                int fast = sflag[t * 128 + px_g];
                if (__all_sync(0xffffffffu, fast)) {
                    #pragma unroll
                    for (int c = 0; c < 4; ++c) {
                        const float* s = sxc + c * (WR * Wn);
                        float v = w4.x * s[p0]       + w4.y * s[p0 + 1]
                                + w4.z * s[p0 + 128] + w4.w * s[p0 + 129];
                        sA[((half * 4 + c) * 9 + t) * 128 + px_g] = v;
                    }
                } else {
                    float dy = offs[(((size_t)(b * 18 + 2 * t)) << 14) + row + px_g];
                    float dx = offs[(((size_t)(b * 18 + 2 * t + 1)) << 14) + row + px_g];
                    int ki = t / 3, kj = t - ki * 3;
                    float py = (float)(h - 1 + ki) + dy;
                    float px = (float)(px_g - 1 + kj) + dx;
                    int y0 = (int)floorf(py), x0 = (int)floorf(px);
                    int ry0 = min(max(y0, 0), Hn - 1) * Wn;
                    int ry1 = min(max(y0 + 1, 0), Hn - 1) * Wn;
                    int cx0 = min(max(x0, 0), Wn - 1);
                    int cx1 = min(max(x0 + 1, 0), Wn - 1);
                    int q0 = ry0 + cx0, q1 = ry0 + cx1;
                    int q2 = ry1 + cx0, q3 = ry1 + cx1;
                    #pragma unroll
                    for (int c = 0; c < 4; ++c) {
                        const float* p = pg + c * HWn;
                        float v = w4.x * __ldg(p + q0) + w4.y * __ldg(p + q1)
                                + w4.z * __ldg(p + q2) + w4.w * __ldg(p + q3);
                        sA[((half * 4 + c) * 9 + t) * 128 + px_g] = v;
                    }
                }
            }
        }
        __syncthreads();

        #pragma unroll 4
        for (int kk = 0; kk < 72; ++kk) {
            float4 av = *(const float4*)&sA[kk * 128 + px4];
            float4 w0 = *(const float4*)&sW[kk * 68 + oc8];
            float4 w1 = *(const float4*)&sW[kk * 68 + oc8 + 4];
            u64 wp[4] = {((const u64*)&w0)[0], ((const u64*)&w0)[1],
                         ((const u64*)&w1)[0], ((const u64*)&w1)[1]};
            float ar[4] = {av.x, av.y, av.z, av.w};
            #pragma unroll
            for (int r = 0; r < 4; ++r) {
                u64 ad = dup2(ar[r]);
                #pragma unroll
                for (int p = 0; p < 4; ++p)
                    acc2[r][p] = fma2(ad, wp[p], acc2[r][p]);
            }
        }
    }

    float acc[4][8];
    #pragma unroll
    for (int r = 0; r < 4; ++r)
        #pragma unroll
        for (int p = 0; p < 4; ++p)
            unpack2(acc2[r][p], acc[r][2 * p], acc[r][2 * p + 1]);

    #pragma unroll
    for (int q = 0; q < 8; ++q) {
        int o = oc8 + q;
        float bias = __ldg(d_b + o);
        float* dst = out + (((size_t)(b * On + o)) << 14) + row;
        float4 v = make_float4(acc[0][q] + bias, acc[1][q] + bias,
                               acc[2][q] + bias, acc[3][q] + bias);
        *(float4*)&dst[px4] = v;
    }
}

// ---------------------------------------------------------------------------

extern "C" void kernel_launch(void* const* d_in, const int* in_sizes, int n_in,
                              void* d_out, int out_size) {
    const float* x    = (const float*)d_in[0];
    const float* p_w  = (const float*)d_in[1];
    const float* p_b  = (const float*)d_in[2];
    const float* m_w  = (const float*)d_in[3];
    const float* m_b  = (const float*)d_in[4];
    const float* d_wp = (const float*)d_in[5];
    const float* d_bp = (const float*)d_in[6];

    float* out = (float*)d_out;                         // [8,64,128,128]
    float* offs_out = out + (size_t)Bn * On * HWn;      // [8,18,128,128]

    const int smemB = 78336 + 8 * WR * Wn * 4 + 258 * 4;   // 112136
    cudaFuncSetAttribute(deform_kernel,
                         cudaFuncAttributeMaxDynamicSharedMemorySize, smemB);

    dim3 gridA(Hn / 2, Bn);
    dim3 gridB(Hn, Bn);
    conv_offmask_kernel<<<gridA, 256>>>(x, p_w, p_b, m_w, m_b, offs_out);
    deform_kernel<<<gridB, 256, smemB>>>(x, offs_out, d_wp, d_bp, out);
}